// round 3
// baseline (speedup 1.0000x reference)
#include <cuda_runtime.h>
#include <cuda_bf16.h>
#include <math_constants.h>
#include <cstdint>

#define Bb  2
#define Ls  4096
#define Ds  512
#define Hh  8
#define HDs 64
#define FFs 2048
#define WIN 128

// ---------------- scratch (device globals: allocation-guard safe) ----------
__device__ float g_q  [Bb*Ls*Ds];
__device__ float g_k  [Bb*Ls*Ds];
__device__ float g_v  [Bb*Ls*Ds];
__device__ float g_att[Bb*Ls*Ds];
__device__ float g_prj[Bb*Ls*Ds];
__device__ float g_h  [Bb*Ls*Ds];
__device__ float g_ff1[Bb*Ls*FFs];
__device__ float g_ff2[Bb*Ls*Ds];

__device__ __forceinline__ uint32_t f2tf(float x) {
    uint32_t u;
    asm("cvt.rna.tf32.f32 %0, %1;" : "=r"(u) : "f"(x));
    return u;
}

__device__ __forceinline__ void mma_tf32(float d[4],
    uint32_t a0, uint32_t a1, uint32_t a2, uint32_t a3,
    uint32_t b0, uint32_t b1)
{
    asm volatile(
        "mma.sync.aligned.m16n8k8.row.col.f32.tf32.tf32.f32 "
        "{%0,%1,%2,%3}, {%4,%5,%6,%7}, {%8,%9}, {%0,%1,%2,%3};\n"
        : "+f"(d[0]), "+f"(d[1]), "+f"(d[2]), "+f"(d[3])
        : "r"(a0), "r"(a1), "r"(a2), "r"(a3), "r"(b0), "r"(b1));
}

// ======================= tf32 tensor-core GEMM ==============================
#define GBM 128
#define GBN 64
#define GBK 32

__global__ __launch_bounds__(128)
void tgemm_bias(const float* __restrict__ A, const float* __restrict__ W,
                const float* __restrict__ bias, float* __restrict__ C,
                int M, int N, int K, int relu)
{
    __shared__ uint32_t As[GBM][GBK + 4];
    __shared__ uint32_t Bs[GBK][GBN + 8];

    const int tid  = threadIdx.x;
    const int lane = tid & 31;
    const int warp = tid >> 5;
    const int gid  = lane >> 2;
    const int tg   = lane & 3;
    const int wm   = (warp >> 1) * 64;
    const int wn   = (warp & 1) * 32;
    const int bm   = blockIdx.y * GBM;
    const int bn   = blockIdx.x * GBN;

    float d[4][4][4];
#pragma unroll
    for (int i = 0; i < 4; i++)
#pragma unroll
        for (int j = 0; j < 4; j++)
#pragma unroll
            for (int c = 0; c < 4; c++) d[i][j][c] = 0.f;

    for (int k0 = 0; k0 < K; k0 += GBK) {
#pragma unroll
        for (int it = 0; it < 8; it++) {
            int idx = tid + it * 128;
            int r = idx >> 3, c4 = (idx & 7) * 4;
            float4 v = *(const float4*)&A[(size_t)(bm + r) * K + k0 + c4];
            uint4 u = make_uint4(f2tf(v.x), f2tf(v.y), f2tf(v.z), f2tf(v.w));
            *(uint4*)&As[r][c4] = u;
        }
#pragma unroll
        for (int it = 0; it < 4; it++) {
            int idx = tid + it * 128;
            int r = idx >> 4, c4 = (idx & 15) * 4;
            float4 v = *(const float4*)&W[(size_t)(k0 + r) * N + bn + c4];
            uint4 u = make_uint4(f2tf(v.x), f2tf(v.y), f2tf(v.z), f2tf(v.w));
            *(uint4*)&Bs[r][c4] = u;
        }
        __syncthreads();

#pragma unroll
        for (int kk = 0; kk < GBK; kk += 8) {
            uint32_t bf[4][2];
#pragma unroll
            for (int jn = 0; jn < 4; jn++) {
                bf[jn][0] = Bs[kk + tg    ][wn + jn * 8 + gid];
                bf[jn][1] = Bs[kk + tg + 4][wn + jn * 8 + gid];
            }
#pragma unroll
            for (int im = 0; im < 4; im++) {
                const int mr = wm + im * 16 + gid;
                uint32_t a0 = As[mr    ][kk + tg    ];
                uint32_t a1 = As[mr + 8][kk + tg    ];
                uint32_t a2 = As[mr    ][kk + tg + 4];
                uint32_t a3 = As[mr + 8][kk + tg + 4];
#pragma unroll
                for (int jn = 0; jn < 4; jn++)
                    mma_tf32(d[im][jn], a0, a1, a2, a3, bf[jn][0], bf[jn][1]);
            }
        }
        __syncthreads();
    }

#pragma unroll
    for (int jn = 0; jn < 4; jn++) {
        const int col = bn + wn + jn * 8 + 2 * tg;
        float2 bv = *(const float2*)&bias[col];
#pragma unroll
        for (int im = 0; im < 4; im++) {
            const int row = bm + wm + im * 16 + gid;
            float2 r0, r1;
            r0.x = d[im][jn][0] + bv.x;  r0.y = d[im][jn][1] + bv.y;
            r1.x = d[im][jn][2] + bv.x;  r1.y = d[im][jn][3] + bv.y;
            if (relu) {
                r0.x = fmaxf(r0.x, 0.f); r0.y = fmaxf(r0.y, 0.f);
                r1.x = fmaxf(r1.x, 0.f); r1.y = fmaxf(r1.y, 0.f);
            }
            *(float2*)&C[(size_t)row       * N + col] = r0;
            *(float2*)&C[(size_t)(row + 8) * N + col] = r1;
        }
    }
}

// ============== banded attention on tensor cores (flash-style) ==============
// One block per (b, h, 64-query tile). 4 warps, each owns 16 query rows.
// Smem: Ps/Qs [64][68], Ks [64][68], Vs [64][72]  (tf32 as uint32)
#define PK_STRIDE 68
#define V_STRIDE  72

__global__ __launch_bounds__(128)
void attn_mma(const float* __restrict__ q, const float* __restrict__ k,
              const float* __restrict__ v, float* __restrict__ out)
{
    extern __shared__ uint32_t sm[];
    uint32_t (*Ps)[PK_STRIDE] = (uint32_t(*)[PK_STRIDE])sm;                 // also Q staging
    uint32_t (*Ks)[PK_STRIDE] = (uint32_t(*)[PK_STRIDE])(sm + 64 * PK_STRIDE);
    uint32_t (*Vs)[V_STRIDE]  = (uint32_t(*)[V_STRIDE]) (sm + 2 * 64 * PK_STRIDE);

    const int bh   = blockIdx.y;
    const int b    = bh >> 3;
    const int h    = bh & 7;
    const int q0   = blockIdx.x * 64;
    const int tid  = threadIdx.x;
    const int lane = tid & 31;
    const int warp = tid >> 5;
    const int gid  = lane >> 2;
    const int tg   = lane & 3;
    const int wm   = warp * 16;

    // ---- stage Q (pre-scaled by 1/sqrt(64)) and load A-fragments ----
#pragma unroll
    for (int it = 0; it < 8; it++) {
        int idx = tid + it * 128;
        int r = idx >> 4, c4 = (idx & 15) * 4;
        float4 t = *(const float4*)&q[((size_t)(b * Ls + q0 + r)) * Ds + h * HDs + c4];
        uint4 u = make_uint4(f2tf(t.x * 0.125f), f2tf(t.y * 0.125f),
                             f2tf(t.z * 0.125f), f2tf(t.w * 0.125f));
        *(uint4*)&Ps[r][c4] = u;
    }
    __syncthreads();

    uint32_t qa[8][4];
#pragma unroll
    for (int ks8 = 0; ks8 < 8; ks8++) {
        qa[ks8][0] = Ps[wm + gid    ][ks8 * 8 + tg    ];
        qa[ks8][1] = Ps[wm + gid + 8][ks8 * 8 + tg    ];
        qa[ks8][2] = Ps[wm + gid    ][ks8 * 8 + tg + 4];
        qa[ks8][3] = Ps[wm + gid + 8][ks8 * 8 + tg + 4];
    }

    float o[8][4];
#pragma unroll
    for (int jn = 0; jn < 8; jn++)
#pragma unroll
        for (int c = 0; c < 4; c++) o[jn][c] = 0.f;
    float m0 = -1e30f, m1 = -1e30f, l0 = 0.f, l1 = 0.f;

    const int row0 = q0 + wm + gid;
    const int row1 = row0 + 8;
    const int kstart = max(0, q0 - WIN);
    const int kend   = min(Ls, q0 + 64 + WIN);

    for (int kt = kstart; kt < kend; kt += 64) {
        __syncthreads();   // previous iteration done reading Ks/Vs
        // ---- stage K, V tiles (tf32) ----
#pragma unroll
        for (int it = 0; it < 8; it++) {
            int idx = tid + it * 128;
            int r = idx >> 4, c4 = (idx & 15) * 4;
            size_t base = ((size_t)(b * Ls + kt + r)) * Ds + h * HDs + c4;
            float4 tk = *(const float4*)&k[base];
            float4 tv = *(const float4*)&v[base];
            *(uint4*)&Ks[r][c4] = make_uint4(f2tf(tk.x), f2tf(tk.y), f2tf(tk.z), f2tf(tk.w));
            *(uint4*)&Vs[r][c4] = make_uint4(f2tf(tv.x), f2tf(tv.y), f2tf(tv.z), f2tf(tv.w));
        }
        __syncthreads();

        // ---- S = Q K^T ----
        float s[8][4];
#pragma unroll
        for (int jn = 0; jn < 8; jn++)
#pragma unroll
            for (int c = 0; c < 4; c++) s[jn][c] = 0.f;

#pragma unroll
        for (int ks8 = 0; ks8 < 8; ks8++) {
#pragma unroll
            for (int jn = 0; jn < 8; jn++) {
                uint32_t b0 = Ks[jn * 8 + gid][ks8 * 8 + tg    ];
                uint32_t b1 = Ks[jn * 8 + gid][ks8 * 8 + tg + 4];
                mma_tf32(s[jn], qa[ks8][0], qa[ks8][1], qa[ks8][2], qa[ks8][3], b0, b1);
            }
        }

        // ---- band mask + row max ----
        float rmax0 = -1e30f, rmax1 = -1e30f;
#pragma unroll
        for (int jn = 0; jn < 8; jn++) {
            int cb = kt + jn * 8 + 2 * tg;
            s[jn][0] = (abs(cb     - row0) <= WIN) ? s[jn][0] : -1e30f;
            s[jn][1] = (abs(cb + 1 - row0) <= WIN) ? s[jn][1] : -1e30f;
            s[jn][2] = (abs(cb     - row1) <= WIN) ? s[jn][2] : -1e30f;
            s[jn][3] = (abs(cb + 1 - row1) <= WIN) ? s[jn][3] : -1e30f;
            rmax0 = fmaxf(rmax0, fmaxf(s[jn][0], s[jn][1]));
            rmax1 = fmaxf(rmax1, fmaxf(s[jn][2], s[jn][3]));
        }
        rmax0 = fmaxf(rmax0, __shfl_xor_sync(0xffffffffu, rmax0, 1));
        rmax0 = fmaxf(rmax0, __shfl_xor_sync(0xffffffffu, rmax0, 2));
        rmax1 = fmaxf(rmax1, __shfl_xor_sync(0xffffffffu, rmax1, 1));
        rmax1 = fmaxf(rmax1, __shfl_xor_sync(0xffffffffu, rmax1, 2));

        // ---- online softmax update ----
        float mn0 = fmaxf(m0, rmax0);
        float mn1 = fmaxf(m1, rmax1);
        float sc0 = __expf(m0 - mn0);
        float sc1 = __expf(m1 - mn1);
        m0 = mn0; m1 = mn1;
        l0 *= sc0; l1 *= sc1;
#pragma unroll
        for (int jn = 0; jn < 8; jn++) {
            o[jn][0] *= sc0; o[jn][1] *= sc0;
            o[jn][2] *= sc1; o[jn][3] *= sc1;
        }

        // ---- P = exp(S - m), accumulate l, write P to smem (tf32) ----
#pragma unroll
        for (int jn = 0; jn < 8; jn++) {
            float p0 = __expf(s[jn][0] - m0);
            float p1 = __expf(s[jn][1] - m0);
            float p2 = __expf(s[jn][2] - m1);
            float p3 = __expf(s[jn][3] - m1);
            l0 += p0 + p1;
            l1 += p2 + p3;
            *(uint2*)&Ps[wm + gid    ][jn * 8 + 2 * tg] = make_uint2(f2tf(p0), f2tf(p1));
            *(uint2*)&Ps[wm + gid + 8][jn * 8 + 2 * tg] = make_uint2(f2tf(p2), f2tf(p3));
        }
        __syncwarp();   // warp reads only its own 16 P rows

        // ---- O += P V ----
#pragma unroll
        for (int ks8 = 0; ks8 < 8; ks8++) {
            uint32_t a0 = Ps[wm + gid    ][ks8 * 8 + tg    ];
            uint32_t a1 = Ps[wm + gid + 8][ks8 * 8 + tg    ];
            uint32_t a2 = Ps[wm + gid    ][ks8 * 8 + tg + 4];
            uint32_t a3 = Ps[wm + gid + 8][ks8 * 8 + tg + 4];
#pragma unroll
            for (int jn = 0; jn < 8; jn++) {
                uint32_t b0 = Vs[ks8 * 8 + tg    ][jn * 8 + gid];
                uint32_t b1 = Vs[ks8 * 8 + tg + 4][jn * 8 + gid];
                mma_tf32(o[jn], a0, a1, a2, a3, b0, b1);
            }
        }
    }

    // ---- finalize ----
    l0 += __shfl_xor_sync(0xffffffffu, l0, 1);
    l0 += __shfl_xor_sync(0xffffffffu, l0, 2);
    l1 += __shfl_xor_sync(0xffffffffu, l1, 1);
    l1 += __shfl_xor_sync(0xffffffffu, l1, 2);
    const float inv0 = 1.f / l0;
    const float inv1 = 1.f / l1;

    float* o0 = out + ((size_t)(b * Ls + row0)) * Ds + h * HDs;
    float* o1 = out + ((size_t)(b * Ls + row1)) * Ds + h * HDs;
#pragma unroll
    for (int jn = 0; jn < 8; jn++) {
        int c = jn * 8 + 2 * tg;
        *(float2*)&o0[c] = make_float2(o[jn][0] * inv0, o[jn][1] * inv0);
        *(float2*)&o1[c] = make_float2(o[jn][2] * inv1, o[jn][3] * inv1);
    }
}

// ---------------- residual + LayerNorm -------------------------------------
__global__ __launch_bounds__(128)
void add_ln(const float* __restrict__ x, const float* __restrict__ r,
            const float* __restrict__ g, const float* __restrict__ bta,
            float* __restrict__ out)
{
    const int row = blockIdx.x;
    const int tid = threadIdx.x;
    const float* xr = x + (size_t)row * Ds;
    const float* rr = r + (size_t)row * Ds;

    __shared__ float t[Ds];
    __shared__ float s1[4], s2[4];

    float s = 0.f, ss = 0.f;
#pragma unroll
    for (int i = 0; i < 4; i++) {
        int c = tid + i * 128;
        float u = xr[c] + rr[c];
        t[c] = u;
        s += u;
        ss = fmaf(u, u, ss);
    }
#pragma unroll
    for (int o = 16; o; o >>= 1) {
        s  += __shfl_xor_sync(0xffffffffu, s,  o);
        ss += __shfl_xor_sync(0xffffffffu, ss, o);
    }
    if ((tid & 31) == 0) { s1[tid >> 5] = s; s2[tid >> 5] = ss; }
    __syncthreads();
    float S  = s1[0] + s1[1] + s1[2] + s1[3];
    float SS = s2[0] + s2[1] + s2[2] + s2[3];
    float mu   = S * (1.f / Ds);
    float var  = SS * (1.f / Ds) - mu * mu;
    float rstd = rsqrtf(var + 1e-5f);
#pragma unroll
    for (int i = 0; i < 4; i++) {
        int c = tid + i * 128;
        out[(size_t)row * Ds + c] = (t[c] - mu) * rstd * g[c] + bta[c];
    }
}

// ---------------- launch ----------------------------------------------------
extern "C" void kernel_launch(void* const* d_in, const int* in_sizes, int n_in,
                              void* d_out, int out_size)
{
    const float* x    = (const float*)d_in[0];
    const float* Wq   = (const float*)d_in[1];
    const float* bq   = (const float*)d_in[2];
    const float* Wk   = (const float*)d_in[3];
    const float* bk   = (const float*)d_in[4];
    const float* Wv   = (const float*)d_in[5];
    const float* bv   = (const float*)d_in[6];
    const float* Wo   = (const float*)d_in[7];
    const float* bo   = (const float*)d_in[8];
    const float* ln1g = (const float*)d_in[9];
    const float* ln1b = (const float*)d_in[10];
    const float* W1   = (const float*)d_in[11];
    const float* b1   = (const float*)d_in[12];
    const float* W2   = (const float*)d_in[13];
    const float* b2   = (const float*)d_in[14];
    const float* ln2g = (const float*)d_in[15];
    const float* ln2b = (const float*)d_in[16];
    float* out = (float*)d_out;

    float *q, *k, *v, *att, *prj, *h, *ff1, *ff2;
    cudaGetSymbolAddress((void**)&q,   g_q);
    cudaGetSymbolAddress((void**)&k,   g_k);
    cudaGetSymbolAddress((void**)&v,   g_v);
    cudaGetSymbolAddress((void**)&att, g_att);
    cudaGetSymbolAddress((void**)&prj, g_prj);
    cudaGetSymbolAddress((void**)&h,   g_h);
    cudaGetSymbolAddress((void**)&ff1, g_ff1);
    cudaGetSymbolAddress((void**)&ff2, g_ff2);

    const int M = Bb * Ls;

    dim3 gD(Ds / GBN, M / GBM);
    dim3 gF(FFs / GBN, M / GBM);

    const int attn_smem = (2 * 64 * PK_STRIDE + 64 * V_STRIDE) * 4;
    cudaFuncSetAttribute(attn_mma, cudaFuncAttributeMaxDynamicSharedMemorySize, attn_smem);

    tgemm_bias<<<gD, 128>>>(x, Wq, bq, q, M, Ds, Ds, 0);
    tgemm_bias<<<gD, 128>>>(x, Wk, bk, k, M, Ds, Ds, 0);
    tgemm_bias<<<gD, 128>>>(x, Wv, bv, v, M, Ds, Ds, 0);

    attn_mma<<<dim3(Ls / 64, Bb * Hh), 128, attn_smem>>>(q, k, v, att);

    tgemm_bias<<<gD, 128>>>(att, Wo, bo, prj, M, Ds, Ds, 0);
    add_ln<<<M, 128>>>(x, prj, ln1g, ln1b, h);

    tgemm_bias<<<gF, 128>>>(h, W1, b1, ff1, M, FFs, Ds, 1);
    tgemm_bias<<<gD, 128>>>(ff1, W2, b2, ff2, M, Ds, FFs, 0);
    add_ln<<<M, 128>>>(h, ff2, ln2g, ln2b, out);
}

// round 4
// speedup vs baseline: 1.7098x; 1.7098x over previous
#include <cuda_runtime.h>
#include <cuda_bf16.h>
#include <math_constants.h>
#include <cstdint>

#define Bb  2
#define Ls  4096
#define Ds  512
#define Hh  8
#define HDs 64
#define FFs 2048
#define WIN 128

// ---------------- scratch (device globals: allocation-guard safe) ----------
__device__ float g_q  [Bb*Ls*Ds];
__device__ float g_k  [Bb*Ls*Ds];
__device__ float g_v  [Bb*Ls*Ds];
__device__ float g_att[Bb*Ls*Ds];
__device__ float g_prj[Bb*Ls*Ds];
__device__ float g_h  [Bb*Ls*Ds];
__device__ float g_ff1[Bb*Ls*FFs];
__device__ float g_ff2[Bb*Ls*Ds];

// ---------------- helpers ---------------------------------------------------
__device__ __forceinline__ void cp16(uint32_t dst_smem, const void* src) {
    asm volatile("cp.async.ca.shared.global [%0], [%1], 16;\n"
                 :: "r"(dst_smem), "l"(src));
}
#define CP_COMMIT() asm volatile("cp.async.commit_group;\n")
#define CP_WAIT(n)  asm volatile("cp.async.wait_group %0;\n" :: "n"(n))

// raw fp32 bits fed to tf32 mma (HW reads top 19 bits; CUTLASS fast path)
__device__ __forceinline__ void mma_tf32(float d[4],
    uint32_t a0, uint32_t a1, uint32_t a2, uint32_t a3,
    uint32_t b0, uint32_t b1)
{
    asm volatile(
        "mma.sync.aligned.m16n8k8.row.col.f32.tf32.tf32.f32 "
        "{%0,%1,%2,%3}, {%4,%5,%6,%7}, {%8,%9}, {%0,%1,%2,%3};\n"
        : "+f"(d[0]), "+f"(d[1]), "+f"(d[2]), "+f"(d[3])
        : "r"(a0), "r"(a1), "r"(a2), "r"(a3), "r"(b0), "r"(b1));
}

// ============ double-buffered cp.async tf32 GEMM ============================
// C[M,N] = A[M,K] @ W[K,N] + bias (optional relu)
// 256 threads, block tile 128x128x32, warp grid 2x4 (warp tile 64x32)
#define BM 128
#define BN 128
#define BK 32
#define ASTRIDE 36     // 4 mod 32  -> conflict-free A frags
#define BSTRIDE 136    // 8 mod 32  -> conflict-free B frags
#define ASZ (BM * ASTRIDE)
#define BSZ (BK * BSTRIDE)
#define STAGE (ASZ + BSZ)
#define GEMM_SMEM (2 * STAGE * 4)

__global__ __launch_bounds__(256)
void tgemm_pipe(const float* __restrict__ A, const float* __restrict__ W,
                const float* __restrict__ bias, float* __restrict__ C,
                int M, int N, int K, int relu)
{
    extern __shared__ uint32_t sh[];
    const uint32_t sbase = (uint32_t)__cvta_generic_to_shared(sh);

    const int tid  = threadIdx.x;
    const int lane = tid & 31;
    const int warp = tid >> 5;
    const int gid  = lane >> 2;
    const int tg   = lane & 3;
    const int wm   = (warp >> 2) * 64;      // 0 / 64
    const int wn   = (warp & 3) * 32;       // 0..96
    const int bm   = blockIdx.y * BM;
    const int bn   = blockIdx.x * BN;

    // cp.async source/dest bases
    const int ar = tid >> 3, ac = (tid & 7) * 4;      // A: 128 rows, 8 f4/row
    const int br = tid >> 5, bc = (tid & 31) * 4;     // B: 32 rows, 32 f4/row
    const float* gA = A + (size_t)(bm + ar) * K + ac;
    const float* gB = W + (size_t)br * N + bn + bc;
    const uint32_t dA = sbase + (ar * ASTRIDE + ac) * 4;
    const uint32_t dB = sbase + (ASZ + br * BSTRIDE + bc) * 4;

    float d[4][4][4];
#pragma unroll
    for (int i = 0; i < 4; i++)
#pragma unroll
        for (int j = 0; j < 4; j++)
#pragma unroll
            for (int c = 0; c < 4; c++) d[i][j][c] = 0.f;

    // prologue: stage 0
#pragma unroll
    for (int i = 0; i < 4; i++) {
        cp16(dA + i * (32 * ASTRIDE * 4), gA + (size_t)i * 32 * K);
        cp16(dB + i * (8 * BSTRIDE * 4),  gB + (size_t)i * 8 * N);
    }
    CP_COMMIT();

    int buf = 0;
    for (int k0 = 0; k0 < K; k0 += BK, buf ^= 1) {
        if (k0 + BK < K) {
            const uint32_t off = (buf ^ 1) * (STAGE * 4);
#pragma unroll
            for (int i = 0; i < 4; i++) {
                cp16(dA + off + i * (32 * ASTRIDE * 4), gA + (size_t)(k0 + BK) + (size_t)i * 32 * K);
                cp16(dB + off + i * (8 * BSTRIDE * 4),  gB + (size_t)(k0 + BK) * N + (size_t)i * 8 * N);
            }
            CP_COMMIT();
            CP_WAIT(1);
        } else {
            CP_WAIT(0);
        }
        __syncthreads();

        const uint32_t* pA = sh + buf * STAGE;
        const uint32_t* pB = sh + buf * STAGE + ASZ;
#pragma unroll
        for (int kk = 0; kk < BK; kk += 8) {
            uint32_t bf[4][2];
#pragma unroll
            for (int jn = 0; jn < 4; jn++) {
                bf[jn][0] = pB[(kk + tg)     * BSTRIDE + wn + jn * 8 + gid];
                bf[jn][1] = pB[(kk + tg + 4) * BSTRIDE + wn + jn * 8 + gid];
            }
#pragma unroll
            for (int im = 0; im < 4; im++) {
                const int mr = wm + im * 16 + gid;
                uint32_t a0 = pA[mr       * ASTRIDE + kk + tg];
                uint32_t a1 = pA[(mr + 8) * ASTRIDE + kk + tg];
                uint32_t a2 = pA[mr       * ASTRIDE + kk + tg + 4];
                uint32_t a3 = pA[(mr + 8) * ASTRIDE + kk + tg + 4];
#pragma unroll
                for (int jn = 0; jn < 4; jn++)
                    mma_tf32(d[im][jn], a0, a1, a2, a3, bf[jn][0], bf[jn][1]);
            }
        }
        __syncthreads();
    }

#pragma unroll
    for (int jn = 0; jn < 4; jn++) {
        const int col = bn + wn + jn * 8 + 2 * tg;
        float2 bv = *(const float2*)&bias[col];
#pragma unroll
        for (int im = 0; im < 4; im++) {
            const int row = bm + wm + im * 16 + gid;
            float2 r0, r1;
            r0.x = d[im][jn][0] + bv.x;  r0.y = d[im][jn][1] + bv.y;
            r1.x = d[im][jn][2] + bv.x;  r1.y = d[im][jn][3] + bv.y;
            if (relu) {
                r0.x = fmaxf(r0.x, 0.f); r0.y = fmaxf(r0.y, 0.f);
                r1.x = fmaxf(r1.x, 0.f); r1.y = fmaxf(r1.y, 0.f);
            }
            *(float2*)&C[(size_t)row       * N + col] = r0;
            *(float2*)&C[(size_t)(row + 8) * N + col] = r1;
        }
    }
}

// ============== banded attention on tensor cores (flash-style) ==============
#define PK_STRIDE 68
#define V_STRIDE  72
#define ATTN_SMEM ((2 * 64 * PK_STRIDE + 64 * V_STRIDE) * 4)

__global__ __launch_bounds__(128)
void attn_mma(const float* __restrict__ q, const float* __restrict__ k,
              const float* __restrict__ v, float* __restrict__ out)
{
    extern __shared__ uint32_t sm[];
    uint32_t (*Ps)[PK_STRIDE] = (uint32_t(*)[PK_STRIDE])sm;
    uint32_t (*Ks)[PK_STRIDE] = (uint32_t(*)[PK_STRIDE])(sm + 64 * PK_STRIDE);
    uint32_t (*Vs)[V_STRIDE]  = (uint32_t(*)[V_STRIDE]) (sm + 2 * 64 * PK_STRIDE);
    const uint32_t sbase = (uint32_t)__cvta_generic_to_shared(sm);
    const uint32_t Ks_off = 64 * PK_STRIDE * 4;
    const uint32_t Vs_off = 2 * 64 * PK_STRIDE * 4;

    const int bh   = blockIdx.y;
    const int b    = bh >> 3;
    const int h    = bh & 7;
    const int q0   = blockIdx.x * 64;
    const int tid  = threadIdx.x;
    const int lane = tid & 31;
    const int warp = tid >> 5;
    const int gid  = lane >> 2;
    const int tg   = lane & 3;
    const int wm   = warp * 16;

    const int sr = tid >> 4, sc = (tid & 15) * 4;   // staging: 8 rows/iter

    // ---- stage Q via cp.async (raw f32 bits; scale folded into S) ----
    {
        const float* gq = q + ((size_t)(b * Ls + q0 + sr)) * Ds + h * HDs + sc;
        const uint32_t dq = sbase + (sr * PK_STRIDE + sc) * 4;
#pragma unroll
        for (int i = 0; i < 8; i++)
            cp16(dq + i * (8 * PK_STRIDE * 4), gq + (size_t)i * 8 * Ds);
    }
    CP_COMMIT();
    CP_WAIT(0);
    __syncthreads();

    uint32_t qa[8][4];
#pragma unroll
    for (int ks8 = 0; ks8 < 8; ks8++) {
        qa[ks8][0] = Ps[wm + gid    ][ks8 * 8 + tg    ];
        qa[ks8][1] = Ps[wm + gid + 8][ks8 * 8 + tg    ];
        qa[ks8][2] = Ps[wm + gid    ][ks8 * 8 + tg + 4];
        qa[ks8][3] = Ps[wm + gid + 8][ks8 * 8 + tg + 4];
    }

    float o[8][4];
#pragma unroll
    for (int jn = 0; jn < 8; jn++)
#pragma unroll
        for (int c = 0; c < 4; c++) o[jn][c] = 0.f;
    float m0 = -1e30f, m1 = -1e30f, l0 = 0.f, l1 = 0.f;

    const int row0 = q0 + wm + gid;
    const int row1 = row0 + 8;
    const int kstart = max(0, q0 - WIN);
    const int kend   = min(Ls, q0 + 64 + WIN);

    for (int kt = kstart; kt < kend; kt += 64) {
        __syncthreads();   // previous iteration done reading Ks/Vs
        {
            const float* gk = k + ((size_t)(b * Ls + kt + sr)) * Ds + h * HDs + sc;
            const float* gv = v + ((size_t)(b * Ls + kt + sr)) * Ds + h * HDs + sc;
            const uint32_t dk = sbase + Ks_off + (sr * PK_STRIDE + sc) * 4;
            const uint32_t dv = sbase + Vs_off + (sr * V_STRIDE  + sc) * 4;
#pragma unroll
            for (int i = 0; i < 8; i++) {
                cp16(dk + i * (8 * PK_STRIDE * 4), gk + (size_t)i * 8 * Ds);
                cp16(dv + i * (8 * V_STRIDE  * 4), gv + (size_t)i * 8 * Ds);
            }
        }
        CP_COMMIT();
        CP_WAIT(0);
        __syncthreads();

        // ---- S = Q K^T ----
        float s[8][4];
#pragma unroll
        for (int jn = 0; jn < 8; jn++)
#pragma unroll
            for (int c = 0; c < 4; c++) s[jn][c] = 0.f;

#pragma unroll
        for (int ks8 = 0; ks8 < 8; ks8++) {
#pragma unroll
            for (int jn = 0; jn < 8; jn++) {
                uint32_t b0 = Ks[jn * 8 + gid][ks8 * 8 + tg    ];
                uint32_t b1 = Ks[jn * 8 + gid][ks8 * 8 + tg + 4];
                mma_tf32(s[jn], qa[ks8][0], qa[ks8][1], qa[ks8][2], qa[ks8][3], b0, b1);
            }
        }

        // ---- scale + band mask + row max ----
        float rmax0 = -1e30f, rmax1 = -1e30f;
#pragma unroll
        for (int jn = 0; jn < 8; jn++) {
            int cb = kt + jn * 8 + 2 * tg;
            s[jn][0] = (abs(cb     - row0) <= WIN) ? s[jn][0] * 0.125f : -1e30f;
            s[jn][1] = (abs(cb + 1 - row0) <= WIN) ? s[jn][1] * 0.125f : -1e30f;
            s[jn][2] = (abs(cb     - row1) <= WIN) ? s[jn][2] * 0.125f : -1e30f;
            s[jn][3] = (abs(cb + 1 - row1) <= WIN) ? s[jn][3] * 0.125f : -1e30f;
            rmax0 = fmaxf(rmax0, fmaxf(s[jn][0], s[jn][1]));
            rmax1 = fmaxf(rmax1, fmaxf(s[jn][2], s[jn][3]));
        }
        rmax0 = fmaxf(rmax0, __shfl_xor_sync(0xffffffffu, rmax0, 1));
        rmax0 = fmaxf(rmax0, __shfl_xor_sync(0xffffffffu, rmax0, 2));
        rmax1 = fmaxf(rmax1, __shfl_xor_sync(0xffffffffu, rmax1, 1));
        rmax1 = fmaxf(rmax1, __shfl_xor_sync(0xffffffffu, rmax1, 2));

        // ---- online softmax update ----
        float mn0 = fmaxf(m0, rmax0);
        float mn1 = fmaxf(m1, rmax1);
        float sc0 = __expf(m0 - mn0);
        float sc1 = __expf(m1 - mn1);
        m0 = mn0; m1 = mn1;
        l0 *= sc0; l1 *= sc1;
#pragma unroll
        for (int jn = 0; jn < 8; jn++) {
            o[jn][0] *= sc0; o[jn][1] *= sc0;
            o[jn][2] *= sc1; o[jn][3] *= sc1;
        }

        // ---- P = exp(S - m), accumulate l, write P (raw f32 bits) ----
#pragma unroll
        for (int jn = 0; jn < 8; jn++) {
            float p0 = __expf(s[jn][0] - m0);
            float p1 = __expf(s[jn][1] - m0);
            float p2 = __expf(s[jn][2] - m1);
            float p3 = __expf(s[jn][3] - m1);
            l0 += p0 + p1;
            l1 += p2 + p3;
            *(uint2*)&Ps[wm + gid    ][jn * 8 + 2 * tg] =
                make_uint2(__float_as_uint(p0), __float_as_uint(p1));
            *(uint2*)&Ps[wm + gid + 8][jn * 8 + 2 * tg] =
                make_uint2(__float_as_uint(p2), __float_as_uint(p3));
        }
        __syncwarp();   // warp reads only its own 16 P rows

        // ---- O += P V ----
#pragma unroll
        for (int ks8 = 0; ks8 < 8; ks8++) {
            uint32_t a0 = Ps[wm + gid    ][ks8 * 8 + tg    ];
            uint32_t a1 = Ps[wm + gid + 8][ks8 * 8 + tg    ];
            uint32_t a2 = Ps[wm + gid    ][ks8 * 8 + tg + 4];
            uint32_t a3 = Ps[wm + gid + 8][ks8 * 8 + tg + 4];
#pragma unroll
            for (int jn = 0; jn < 8; jn++) {
                uint32_t b0 = Vs[ks8 * 8 + tg    ][jn * 8 + gid];
                uint32_t b1 = Vs[ks8 * 8 + tg + 4][jn * 8 + gid];
                mma_tf32(o[jn], a0, a1, a2, a3, b0, b1);
            }
        }
    }

    // ---- finalize ----
    l0 += __shfl_xor_sync(0xffffffffu, l0, 1);
    l0 += __shfl_xor_sync(0xffffffffu, l0, 2);
    l1 += __shfl_xor_sync(0xffffffffu, l1, 1);
    l1 += __shfl_xor_sync(0xffffffffu, l1, 2);
    const float inv0 = 1.f / l0;
    const float inv1 = 1.f / l1;

    float* o0 = out + ((size_t)(b * Ls + row0)) * Ds + h * HDs;
    float* o1 = out + ((size_t)(b * Ls + row1)) * Ds + h * HDs;
#pragma unroll
    for (int jn = 0; jn < 8; jn++) {
        int c = jn * 8 + 2 * tg;
        *(float2*)&o0[c] = make_float2(o[jn][0] * inv0, o[jn][1] * inv0);
        *(float2*)&o1[c] = make_float2(o[jn][2] * inv1, o[jn][3] * inv1);
    }
}

// ---------------- residual + LayerNorm -------------------------------------
__global__ __launch_bounds__(128)
void add_ln(const float* __restrict__ x, const float* __restrict__ r,
            const float* __restrict__ g, const float* __restrict__ bta,
            float* __restrict__ out)
{
    const int row = blockIdx.x;
    const int tid = threadIdx.x;
    const float* xr = x + (size_t)row * Ds;
    const float* rr = r + (size_t)row * Ds;

    __shared__ float t[Ds];
    __shared__ float s1[4], s2[4];

    float s = 0.f, ss = 0.f;
#pragma unroll
    for (int i = 0; i < 4; i++) {
        int c = tid + i * 128;
        float u = xr[c] + rr[c];
        t[c] = u;
        s += u;
        ss = fmaf(u, u, ss);
    }
#pragma unroll
    for (int o = 16; o; o >>= 1) {
        s  += __shfl_xor_sync(0xffffffffu, s,  o);
        ss += __shfl_xor_sync(0xffffffffu, ss, o);
    }
    if ((tid & 31) == 0) { s1[tid >> 5] = s; s2[tid >> 5] = ss; }
    __syncthreads();
    float S  = s1[0] + s1[1] + s1[2] + s1[3];
    float SS = s2[0] + s2[1] + s2[2] + s2[3];
    float mu   = S * (1.f / Ds);
    float var  = SS * (1.f / Ds) - mu * mu;
    float rstd = rsqrtf(var + 1e-5f);
#pragma unroll
    for (int i = 0; i < 4; i++) {
        int c = tid + i * 128;
        out[(size_t)row * Ds + c] = (t[c] - mu) * rstd * g[c] + bta[c];
    }
}

// ---------------- launch ----------------------------------------------------
extern "C" void kernel_launch(void* const* d_in, const int* in_sizes, int n_in,
                              void* d_out, int out_size)
{
    const float* x    = (const float*)d_in[0];
    const float* Wq   = (const float*)d_in[1];
    const float* bq   = (const float*)d_in[2];
    const float* Wk   = (const float*)d_in[3];
    const float* bk   = (const float*)d_in[4];
    const float* Wv   = (const float*)d_in[5];
    const float* bv   = (const float*)d_in[6];
    const float* Wo   = (const float*)d_in[7];
    const float* bo   = (const float*)d_in[8];
    const float* ln1g = (const float*)d_in[9];
    const float* ln1b = (const float*)d_in[10];
    const float* W1   = (const float*)d_in[11];
    const float* b1   = (const float*)d_in[12];
    const float* W2   = (const float*)d_in[13];
    const float* b2   = (const float*)d_in[14];
    const float* ln2g = (const float*)d_in[15];
    const float* ln2b = (const float*)d_in[16];
    float* out = (float*)d_out;

    float *q, *k, *v, *att, *prj, *h, *ff1, *ff2;
    cudaGetSymbolAddress((void**)&q,   g_q);
    cudaGetSymbolAddress((void**)&k,   g_k);
    cudaGetSymbolAddress((void**)&v,   g_v);
    cudaGetSymbolAddress((void**)&att, g_att);
    cudaGetSymbolAddress((void**)&prj, g_prj);
    cudaGetSymbolAddress((void**)&h,   g_h);
    cudaGetSymbolAddress((void**)&ff1, g_ff1);
    cudaGetSymbolAddress((void**)&ff2, g_ff2);

    const int M = Bb * Ls;

    static int attr_done = 0;
    cudaFuncSetAttribute(tgemm_pipe, cudaFuncAttributeMaxDynamicSharedMemorySize, GEMM_SMEM);
    cudaFuncSetAttribute(attn_mma,  cudaFuncAttributeMaxDynamicSharedMemorySize, ATTN_SMEM);
    (void)attr_done;

    dim3 gD(Ds / BN, M / BM);     // 4 x 64
    dim3 gF(FFs / BN, M / BM);    // 16 x 64

    tgemm_pipe<<<gD, 256, GEMM_SMEM>>>(x, Wq, bq, q, M, Ds, Ds, 0);
    tgemm_pipe<<<gD, 256, GEMM_SMEM>>>(x, Wk, bk, k, M, Ds, Ds, 0);
    tgemm_pipe<<<gD, 256, GEMM_SMEM>>>(x, Wv, bv, v, M, Ds, Ds, 0);

    attn_mma<<<dim3(Ls / 64, Bb * Hh), 128, ATTN_SMEM>>>(q, k, v, att);

    tgemm_pipe<<<gD, 256, GEMM_SMEM>>>(att, Wo, bo, prj, M, Ds, Ds, 0);
    add_ln<<<M, 128>>>(x, prj, ln1g, ln1b, h);

    tgemm_pipe<<<gF, 256, GEMM_SMEM>>>(h, W1, b1, ff1, M, FFs, Ds, 1);
    tgemm_pipe<<<gD, 256, GEMM_SMEM>>>(ff1, W2, b2, ff2, M, Ds, FFs, 0);
    add_ln<<<M, 128>>>(h, ff2, ln2g, ln2b, out);
}